// round 16
// baseline (speedup 1.0000x reference)
#include <cuda_runtime.h>
#include <cuda_fp16.h>
#include <cstdint>

#define BLOCK 128
#define ITERS 8

// dynamic smem layout (bytes)
#define SMEM_SW0 0        // 1024 half = 2048 B
#define SMEM_SW1 2048     // 1024 half = 2048 B
#define SMEM_SWO 4096     // 64 half = 128 B
#define SMEM_SB0 4224     // 32 float
#define SMEM_SB1 4352     // 32 float
#define SMEM_SBO 4480     // 2 float
#define SMEM_X   4608     // 2 bufs * 4 warps * 4096 B
#define SMEM_TOTAL (4608 + 2 * 4 * 4096)

typedef unsigned long long ull;

// m16n8k16 row.col f16*f16+f32
__device__ __forceinline__ void mma16816(float& c0, float& c1, float& c2, float& c3,
                                         unsigned a0, unsigned a1, unsigned a2, unsigned a3,
                                         unsigned b0, unsigned b1) {
    asm("mma.sync.aligned.m16n8k16.row.col.f32.f16.f16.f32 "
        "{%0,%1,%2,%3}, {%4,%5,%6,%7}, {%8,%9}, {%0,%1,%2,%3};"
        : "+f"(c0), "+f"(c1), "+f"(c2), "+f"(c3)
        : "r"(a0), "r"(a1), "r"(a2), "r"(a3), "r"(b0), "r"(b1));
}

__device__ __forceinline__ ull sub2(ull a, ull b) {
    ull d; asm("sub.rn.f32x2 %0, %1, %2;" : "=l"(d) : "l"(a), "l"(b)); return d;
}
__device__ __forceinline__ ull pack2(float lo, float hi) {
    ull r; asm("mov.b64 %0, {%1, %2};" : "=l"(r) : "f"(lo), "f"(hi)); return r;
}
__device__ __forceinline__ void unpack2(ull v, float& lo, float& hi) {
    asm("mov.b64 {%0, %1}, %2;" : "=f"(lo), "=f"(hi) : "l"(v));
}
__device__ __forceinline__ unsigned h2u(__half2 h) { return *reinterpret_cast<unsigned*>(&h); }
__device__ __forceinline__ unsigned packh2(float lo, float hi) {
    return h2u(__float22half2_rn(make_float2(lo, hi)));
}

// +0.5 pre-folded into hidden biases: accumulator holds v+0.5, and
// qrelu(v) = trunc(max(v,0)+0.5) = trunc(max(v+0.5, 0.5))
__device__ __forceinline__ float qrelu_p(float vp) { return truncf(fmaxf(vp, 0.5f)); }
// signed quantize, no relu (final layer)
__device__ __forceinline__ float qfin(float v)  { return truncf(v + copysignf(0.5f, v)); }

__device__ __forceinline__ void cp16(unsigned dst, const void* src) {
    asm volatile("cp.async.cg.shared.global [%0], [%1], 16;" :: "r"(dst), "l"(src));
}

template <bool GUARD>
__global__ void __launch_bounds__(BLOCK, 5) armint_kernel(
    const float* __restrict__ x,
    const float* __restrict__ w0, const float* __restrict__ b0,
    const float* __restrict__ w1, const float* __restrict__ b1,
    const float* __restrict__ w_out, const float* __restrict__ b_out,
    float* __restrict__ out, int B)
{
    extern __shared__ char smem[];
    __half* sw0 = (__half*)(smem + SMEM_SW0);
    __half* sw1 = (__half*)(smem + SMEM_SW1);
    __half* swo = (__half*)(smem + SMEM_SWO);
    float*  sb0 = (float*)(smem + SMEM_SB0);
    float*  sb1 = (float*)(smem + SMEM_SB1);
    float*  sbo = (float*)(smem + SMEM_SBO);

    // All scaling folded into weights (exact exponent shifts on integers):
    //   layer1: A = x, W0' = W0 + 256I   -> y1 = xx1/256
    //   layer2: W1'' = (W1 + 256I)/256   -> y2 = xx2/256
    //   layer3: Wo'' = Wout/256          -> y3 = xx3/256
    // Hidden biases staged as b/256 + 0.5 (rounding offset folded in).
    // sw0 COLUMN-PERMUTED: MMA k-pos p (=2t+e+8b) <- feature sigma(p)=4t+2b+e
    for (int i = threadIdx.x; i < 1024; i += BLOCK) {
        int n = i >> 5, kidx = i & 31;
        int kt = kidx >> 4, p = kidx & 15;
        int tt = (p >> 1) & 3, e = p & 1, bb = (p >> 3) & 1;
        int src = kt * 16 + 4 * tt + 2 * bb + e;       // sigma
        sw0[i] = __float2half_rn(w0[n * 32 + src] + (n == src ? 256.f : 0.f));
        sw1[i] = __float2half_rn((w1[i] + (n == kidx ? 256.f : 0.f)) * 0.00390625f);
    }
    if (threadIdx.x < 64) swo[threadIdx.x] = __float2half_rn(w_out[threadIdx.x] * 0.00390625f);
    if (threadIdx.x < 32) {
        sb0[threadIdx.x] = fmaf(b0[threadIdx.x], 0.00390625f, 0.5f);
        sb1[threadIdx.x] = fmaf(b1[threadIdx.x], 0.00390625f, 0.5f);
    }
    if (threadIdx.x < 2)  sbo[threadIdx.x] = b_out[threadIdx.x] * 0.00390625f;
    __syncthreads();

    const int warp = threadIdx.x >> 5;
    const int lane = threadIdx.x & 31;
    const int g = lane >> 2;   // 0..7
    const int t = lane & 3;    // 0..3

    // persistent per-thread weight fragments
    unsigned WB0[2][4][2], WB1[2][4][2], WB2[2][2];
    #pragma unroll
    for (int kt = 0; kt < 2; kt++)
        #pragma unroll
        for (int nt = 0; nt < 4; nt++) {
            int n = 8 * nt + g, k0 = 16 * kt + 2 * t;
            WB0[kt][nt][0] = *(const unsigned*)&sw0[n * 32 + k0];
            WB0[kt][nt][1] = *(const unsigned*)&sw0[n * 32 + k0 + 8];
            WB1[kt][nt][0] = *(const unsigned*)&sw1[n * 32 + k0];
            WB1[kt][nt][1] = *(const unsigned*)&sw1[n * 32 + k0 + 8];
        }
    #pragma unroll
    for (int kt = 0; kt < 2; kt++) {
        int k0 = 16 * kt + 2 * t;
        if (g < 2) {
            WB2[kt][0] = *(const unsigned*)&swo[g * 32 + k0];
            WB2[kt][1] = *(const unsigned*)&swo[g * 32 + k0 + 8];
        } else { WB2[kt][0] = 0u; WB2[kt][1] = 0u; }
    }
    // persistent biases (hidden: pre-shifted by +0.5)
    float be0[4], bo0[4], be1[4], bo1[4];
    #pragma unroll
    for (int nt = 0; nt < 4; nt++) {
        be0[nt] = sb0[8 * nt + 2 * t]; bo0[nt] = sb0[8 * nt + 2 * t + 1];
        be1[nt] = sb1[8 * nt + 2 * t]; bo1[nt] = sb1[8 * nt + 2 * t + 1];
    }
    const float beo = sbo[0];
    const float boo = sbo[1];

    const int rb0 = blockIdx.x * (128 * ITERS) + warp * 32;

    // per-warp private x staging: 2 buffers x 4096 B.
    // swizzle: row rl (0..31) half kt at rl*128 + ((kt ^ (rl&1))<<6) + t*16
    // -> each LDS.128 phase covers all 32 banks (conflict-free)
    char* xwarp = smem + SMEM_X + warp * 4096;
    unsigned xbase0 = (unsigned)__cvta_generic_to_shared(xwarp);
    const unsigned bufstride = 4 * 4096;

    #define ISSUE_TILE(rbase, b)                                                   \
    do {                                                                           \
        unsigned dstb = xbase0 + (b) * bufstride;                                  \
        _Pragma("unroll")                                                          \
        for (int mt = 0; mt < 2; mt++)                                             \
            _Pragma("unroll")                                                      \
            for (int rh = 0; rh < 2; rh++) {                                       \
                int rl = 16 * mt + g + 8 * rh;                                     \
                int row = (rbase) + rl;                                            \
                if (GUARD && row >= B) row = B - 1;                                \
                const float* src = x + (size_t)row * 32 + 4 * t;                   \
                _Pragma("unroll")                                                  \
                for (int kt = 0; kt < 2; kt++)                                     \
                    cp16(dstb + rl * 128 + ((kt ^ (rl & 1)) << 6) + t * 16,        \
                         src + kt * 16);                                           \
            }                                                                      \
        asm volatile("cp.async.commit_group;" ::: "memory");                       \
    } while (0)

    // prologue: stage tile 0 into buffer 0
    ISSUE_TILE(rb0, 0);

    for (int it = 0; it < ITERS; it++) {
        const int rb = rb0 + it * 128;
        const int cur = it & 1;

        if (it + 1 < ITERS) {
            ISSUE_TILE(rb + 128, cur ^ 1);
            asm volatile("cp.async.wait_group 1;" ::: "memory");
        } else {
            asm volatile("cp.async.wait_group 0;" ::: "memory");
        }
        // no __syncwarp needed: each thread reads only bytes it staged itself

        const char* xbuf = xwarp + cur * bufstride;

        // process the two mtiles sequentially (halves live registers)
        #pragma unroll
        for (int mt = 0; mt < 2; mt++) {
            // ---- convert staged x -> hi/lo f16 A fragments ----
            unsigned AH[2][4], AL[2][4];
            #pragma unroll
            for (int rh = 0; rh < 2; rh++) {
                int rl = 16 * mt + g + 8 * rh;
                #pragma unroll
                for (int kt = 0; kt < 2; kt++) {
                    float4 v = *(const float4*)(xbuf + rl * 128 +
                                                ((kt ^ (rl & 1)) << 6) + t * 16);
                    __half2 h01 = __float22half2_rn(make_float2(v.x, v.y));
                    float2 hb01 = __half22float2(h01);
                    ull l01 = sub2(pack2(v.x, v.y), pack2(hb01.x, hb01.y));
                    __half2 h23 = __float22half2_rn(make_float2(v.z, v.w));
                    float2 hb23 = __half22float2(h23);
                    ull l23 = sub2(pack2(v.z, v.w), pack2(hb23.x, hb23.y));
                    float la, lb;
                    AH[kt][rh]     = h2u(h01);
                    AH[kt][2 + rh] = h2u(h23);
                    unpack2(l01, la, lb); AL[kt][rh]     = packh2(la, lb);
                    unpack2(l23, la, lb); AL[kt][2 + rh] = packh2(la, lb);
                }
            }

            // ---- layer 1 (bias+0.5 as accumulator init) ----
            float C[4][4];
            #pragma unroll
            for (int nt = 0; nt < 4; nt++) {
                C[nt][0] = be0[nt]; C[nt][1] = bo0[nt];
                C[nt][2] = be0[nt]; C[nt][3] = bo0[nt];
                #pragma unroll
                for (int kt = 0; kt < 2; kt++) {
                    mma16816(C[nt][0], C[nt][1], C[nt][2], C[nt][3],
                             AH[kt][0], AH[kt][1], AH[kt][2], AH[kt][3],
                             WB0[kt][nt][0], WB0[kt][nt][1]);
                    mma16816(C[nt][0], C[nt][1], C[nt][2], C[nt][3],
                             AL[kt][0], AL[kt][1], AL[kt][2], AL[kt][3],
                             WB0[kt][nt][0], WB0[kt][nt][1]);
                }
            }

            // ---- quantize -> layer-2 A fragments ----
            unsigned A[2][4];
            #pragma unroll
            for (int kn = 0; kn < 2; kn++) {
                int n0 = 2 * kn, n1 = 2 * kn + 1;
                A[kn][0] = packh2(qrelu_p(C[n0][0]), qrelu_p(C[n0][1]));
                A[kn][1] = packh2(qrelu_p(C[n0][2]), qrelu_p(C[n0][3]));
                A[kn][2] = packh2(qrelu_p(C[n1][0]), qrelu_p(C[n1][1]));
                A[kn][3] = packh2(qrelu_p(C[n1][2]), qrelu_p(C[n1][3]));
            }

            // ---- layer 2 ----
            #pragma unroll
            for (int nt = 0; nt < 4; nt++) {
                C[nt][0] = be1[nt]; C[nt][1] = bo1[nt];
                C[nt][2] = be1[nt]; C[nt][3] = bo1[nt];
                #pragma unroll
                for (int kt = 0; kt < 2; kt++)
                    mma16816(C[nt][0], C[nt][1], C[nt][2], C[nt][3],
                             A[kt][0], A[kt][1], A[kt][2], A[kt][3],
                             WB1[kt][nt][0], WB1[kt][nt][1]);
            }

            #pragma unroll
            for (int kn = 0; kn < 2; kn++) {
                int n0 = 2 * kn, n1 = 2 * kn + 1;
                A[kn][0] = packh2(qrelu_p(C[n0][0]), qrelu_p(C[n0][1]));
                A[kn][1] = packh2(qrelu_p(C[n0][2]), qrelu_p(C[n0][3]));
                A[kn][2] = packh2(qrelu_p(C[n1][0]), qrelu_p(C[n1][1]));
                A[kn][3] = packh2(qrelu_p(C[n1][2]), qrelu_p(C[n1][3]));
            }

            // ---- layer 3: outputs live in cols 0/1 of t==0 lanes ----
            float D[4];
            D[0] = beo; D[1] = boo; D[2] = beo; D[3] = boo;
            #pragma unroll
            for (int kt = 0; kt < 2; kt++)
                mma16816(D[0], D[1], D[2], D[3],
                         A[kt][0], A[kt][1], A[kt][2], A[kt][3],
                         WB2[kt][0], WB2[kt][1]);

            // ---- epilogue: raw = qfin(y3)/256 ----
            if (t == 0) {
                #pragma unroll
                for (int half = 0; half < 2; half++) {
                    int row = rb + 16 * mt + g + (half ? 8 : 0);
                    float mu = qfin(D[half ? 2 : 0]) * 0.00390625f;
                    float ls = qfin(D[half ? 3 : 1]) * 0.00390625f;
                    float sc = __expf(fminf(fmaxf(ls - 4.0f, -4.6f), 5.0f));
                    if (!GUARD || row < B) {
                        out[row]                 = mu;
                        out[B + row]             = sc;
                        out[2 * (size_t)B + row] = ls;
                    }
                }
            }
        }
    }
    #undef ISSUE_TILE
}

extern "C" void kernel_launch(void* const* d_in, const int* in_sizes, int n_in,
                              void* d_out, int out_size)
{
    const float* x     = (const float*)d_in[0];
    const float* w0    = (const float*)d_in[1];
    const float* b0    = (const float*)d_in[2];
    const float* w1    = (const float*)d_in[3];
    const float* b1    = (const float*)d_in[4];
    const float* w_out = (const float*)d_in[5];
    const float* b_out = (const float*)d_in[6];

    const int B = in_sizes[0] / 32;
    const int rows_per_block = 128 * ITERS;
    const int grid = (B + rows_per_block - 1) / rows_per_block;

    if (B % rows_per_block == 0) {
        cudaFuncSetAttribute(armint_kernel<false>,
                             cudaFuncAttributeMaxDynamicSharedMemorySize, SMEM_TOTAL);
        armint_kernel<false><<<grid, BLOCK, SMEM_TOTAL>>>(
            x, w0, b0, w1, b1, w_out, b_out, (float*)d_out, B);
    } else {
        cudaFuncSetAttribute(armint_kernel<true>,
                             cudaFuncAttributeMaxDynamicSharedMemorySize, SMEM_TOTAL);
        armint_kernel<true><<<grid, BLOCK, SMEM_TOTAL>>>(
            x, w0, b0, w1, b1, w_out, b_out, (float*)d_out, B);
    }
}

// round 17
// speedup vs baseline: 1.0912x; 1.0912x over previous
#include <cuda_runtime.h>
#include <cuda_fp16.h>
#include <cstdint>

#define BLOCK 128
#define ITERS 8

// dynamic smem layout (bytes)
#define SMEM_SW0 0        // 1024 half = 2048 B
#define SMEM_SW1 2048     // 1024 half = 2048 B
#define SMEM_SWO 4096     // 64 half = 128 B
#define SMEM_SB0 4224     // 32 float
#define SMEM_SB1 4352     // 32 float
#define SMEM_SBO 4480     // 2 float
#define SMEM_X   4608     // 2 bufs * 4 warps * 4096 B
#define SMEM_TOTAL (4608 + 2 * 4 * 4096)

typedef unsigned long long ull;

// m16n8k16 row.col f16*f16+f32
__device__ __forceinline__ void mma16816(float& c0, float& c1, float& c2, float& c3,
                                         unsigned a0, unsigned a1, unsigned a2, unsigned a3,
                                         unsigned b0, unsigned b1) {
    asm("mma.sync.aligned.m16n8k16.row.col.f32.f16.f16.f32 "
        "{%0,%1,%2,%3}, {%4,%5,%6,%7}, {%8,%9}, {%0,%1,%2,%3};"
        : "+f"(c0), "+f"(c1), "+f"(c2), "+f"(c3)
        : "r"(a0), "r"(a1), "r"(a2), "r"(a3), "r"(b0), "r"(b1));
}

__device__ __forceinline__ ull sub2(ull a, ull b) {
    ull d; asm("sub.rn.f32x2 %0, %1, %2;" : "=l"(d) : "l"(a), "l"(b)); return d;
}
__device__ __forceinline__ ull pack2(float lo, float hi) {
    ull r; asm("mov.b64 %0, {%1, %2};" : "=l"(r) : "f"(lo), "f"(hi)); return r;
}
__device__ __forceinline__ void unpack2(ull v, float& lo, float& hi) {
    asm("mov.b64 {%0, %1}, %2;" : "=f"(lo), "=f"(hi) : "l"(v));
}
__device__ __forceinline__ unsigned h2u(__half2 h) { return *reinterpret_cast<unsigned*>(&h); }
__device__ __forceinline__ unsigned packh2(float lo, float hi) {
    return h2u(__float22half2_rn(make_float2(lo, hi)));
}

// working in xx/256 units: relu+quantize is trunc(max(v,0)+0.5)
__device__ __forceinline__ float qrelu_p(float vp) { return truncf(fmaxf(vp, 0.5f)); }
// signed quantize, no relu (final layer)
__device__ __forceinline__ float qfin(float v)  { return truncf(v + copysignf(0.5f, v)); }

__device__ __forceinline__ void cp16(unsigned dst, const void* src) {
    asm volatile("cp.async.cg.shared.global [%0], [%1], 16;" :: "r"(dst), "l"(src));
}

template <bool GUARD>
__global__ void __launch_bounds__(BLOCK, 5) armint_kernel(
    const float* __restrict__ x,
    const float* __restrict__ w0, const float* __restrict__ b0,
    const float* __restrict__ w1, const float* __restrict__ b1,
    const float* __restrict__ w_out, const float* __restrict__ b_out,
    float* __restrict__ out, long long B)
{
    extern __shared__ char smem[];
    __half* sw0 = (__half*)(smem + SMEM_SW0);
    __half* sw1 = (__half*)(smem + SMEM_SW1);
    __half* swo = (__half*)(smem + SMEM_SWO);
    float*  sb0 = (float*)(smem + SMEM_SB0);
    float*  sb1 = (float*)(smem + SMEM_SB1);
    float*  sbo = (float*)(smem + SMEM_SBO);

    // All scaling folded into weights (exact exponent shifts on integers):
    //   layer1: A = x, W0' = W0 + 256I   -> y1 = xx1/256
    //   layer2: W1'' = (W1 + 256I)/256   -> y2 = xx2/256
    //   layer3: Wo'' = Wout/256          -> y3 = xx3/256
    // Hidden biases staged as b/256 + 0.5 (rounding offset folded in).
    // sw0 COLUMN-PERMUTED: MMA k-pos p (=2t+e+8b) <- feature sigma(p)=4t+2b+e
    for (int i = threadIdx.x; i < 1024; i += BLOCK) {
        int n = i >> 5, kidx = i & 31;
        int kt = kidx >> 4, p = kidx & 15;
        int tt = (p >> 1) & 3, e = p & 1, bb = (p >> 3) & 1;
        int src = kt * 16 + 4 * tt + 2 * bb + e;       // sigma
        sw0[i] = __float2half_rn(w0[n * 32 + src] + (n == src ? 256.f : 0.f));
        sw1[i] = __float2half_rn((w1[i] + (n == kidx ? 256.f : 0.f)) * 0.00390625f);
    }
    if (threadIdx.x < 64) swo[threadIdx.x] = __float2half_rn(w_out[threadIdx.x] * 0.00390625f);
    if (threadIdx.x < 32) {
        sb0[threadIdx.x] = fmaf(b0[threadIdx.x], 0.00390625f, 0.5f);
        sb1[threadIdx.x] = fmaf(b1[threadIdx.x], 0.00390625f, 0.5f);
    }
    if (threadIdx.x < 2)  sbo[threadIdx.x] = b_out[threadIdx.x] * 0.00390625f;
    __syncthreads();

    const int warp = threadIdx.x >> 5;
    const int lane = threadIdx.x & 31;
    const int g = lane >> 2;   // 0..7
    const int t = lane & 3;    // 0..3

    // persistent per-thread weight fragments
    unsigned WB0[2][4][2], WB1[2][4][2], WB2[2][2];
    #pragma unroll
    for (int kt = 0; kt < 2; kt++)
        #pragma unroll
        for (int nt = 0; nt < 4; nt++) {
            int n = 8 * nt + g, k0 = 16 * kt + 2 * t;
            WB0[kt][nt][0] = *(const unsigned*)&sw0[n * 32 + k0];
            WB0[kt][nt][1] = *(const unsigned*)&sw0[n * 32 + k0 + 8];
            WB1[kt][nt][0] = *(const unsigned*)&sw1[n * 32 + k0];
            WB1[kt][nt][1] = *(const unsigned*)&sw1[n * 32 + k0 + 8];
        }
    #pragma unroll
    for (int kt = 0; kt < 2; kt++) {
        int k0 = 16 * kt + 2 * t;
        if (g < 2) {
            WB2[kt][0] = *(const unsigned*)&swo[g * 32 + k0];
            WB2[kt][1] = *(const unsigned*)&swo[g * 32 + k0 + 8];
        } else { WB2[kt][0] = 0u; WB2[kt][1] = 0u; }
    }
    // persistent biases (hidden: pre-shifted by +0.5)
    float be0[4], bo0[4], be1[4], bo1[4];
    #pragma unroll
    for (int nt = 0; nt < 4; nt++) {
        be0[nt] = sb0[8 * nt + 2 * t]; bo0[nt] = sb0[8 * nt + 2 * t + 1];
        be1[nt] = sb1[8 * nt + 2 * t]; bo1[nt] = sb1[8 * nt + 2 * t + 1];
    }
    const float beo = sbo[0];
    const float boo = sbo[1];

    const long long rb0 = (long long)blockIdx.x * (128LL * ITERS) + (long long)warp * 32;

    // per-warp private x staging: 2 buffers x 4096 B.
    // swizzle: row rl (0..31) half kt at rl*128 + ((kt ^ (rl&1))<<6) + t*16
    // -> each LDS.128 phase covers all 32 banks (conflict-free)
    char* xwarp = smem + SMEM_X + warp * 4096;
    unsigned xbase0 = (unsigned)__cvta_generic_to_shared(xwarp);
    const unsigned bufstride = 4 * 4096;

    #define ISSUE_TILE(rbase, b)                                                   \
    do {                                                                           \
        unsigned dstb = xbase0 + (b) * bufstride;                                  \
        _Pragma("unroll")                                                          \
        for (int mt = 0; mt < 2; mt++)                                             \
            _Pragma("unroll")                                                      \
            for (int rh = 0; rh < 2; rh++) {                                       \
                int rl = 16 * mt + g + 8 * rh;                                     \
                long long row = (rbase) + rl;                                      \
                if (GUARD && row >= B) row = B - 1;                                \
                const float* src = x + row * 32 + 4 * t;                           \
                _Pragma("unroll")                                                  \
                for (int kt = 0; kt < 2; kt++)                                     \
                    cp16(dstb + rl * 128 + ((kt ^ (rl & 1)) << 6) + t * 16,        \
                         src + kt * 16);                                           \
            }                                                                      \
        asm volatile("cp.async.commit_group;" ::: "memory");                       \
    } while (0)

    // prologue: stage tile 0 into buffer 0
    ISSUE_TILE(rb0, 0);

    for (int it = 0; it < ITERS; it++) {
        const long long rb = rb0 + (long long)it * 128;
        const int cur = it & 1;

        if (it + 1 < ITERS) {
            ISSUE_TILE(rb + 128, cur ^ 1);
            asm volatile("cp.async.wait_group 1;" ::: "memory");
        } else {
            asm volatile("cp.async.wait_group 0;" ::: "memory");
        }
        // no __syncwarp needed: each thread reads only bytes it staged itself

        const char* xbuf = xwarp + cur * bufstride;

        // process the two mtiles sequentially (halves live registers)
        #pragma unroll
        for (int mt = 0; mt < 2; mt++) {
            // ---- convert staged x -> hi/lo f16 A fragments ----
            unsigned AH[2][4], AL[2][4];
            #pragma unroll
            for (int rh = 0; rh < 2; rh++) {
                int rl = 16 * mt + g + 8 * rh;
                #pragma unroll
                for (int kt = 0; kt < 2; kt++) {
                    float4 v = *(const float4*)(xbuf + rl * 128 +
                                                ((kt ^ (rl & 1)) << 6) + t * 16);
                    __half2 h01 = __float22half2_rn(make_float2(v.x, v.y));
                    float2 hb01 = __half22float2(h01);
                    ull l01 = sub2(pack2(v.x, v.y), pack2(hb01.x, hb01.y));
                    __half2 h23 = __float22half2_rn(make_float2(v.z, v.w));
                    float2 hb23 = __half22float2(h23);
                    ull l23 = sub2(pack2(v.z, v.w), pack2(hb23.x, hb23.y));
                    float la, lb;
                    AH[kt][rh]     = h2u(h01);
                    AH[kt][2 + rh] = h2u(h23);
                    unpack2(l01, la, lb); AL[kt][rh]     = packh2(la, lb);
                    unpack2(l23, la, lb); AL[kt][2 + rh] = packh2(la, lb);
                }
            }

            // ---- layer 1 (bias+0.5 as accumulator init) ----
            float C[4][4];
            #pragma unroll
            for (int nt = 0; nt < 4; nt++) {
                C[nt][0] = be0[nt]; C[nt][1] = bo0[nt];
                C[nt][2] = be0[nt]; C[nt][3] = bo0[nt];
                #pragma unroll
                for (int kt = 0; kt < 2; kt++) {
                    mma16816(C[nt][0], C[nt][1], C[nt][2], C[nt][3],
                             AH[kt][0], AH[kt][1], AH[kt][2], AH[kt][3],
                             WB0[kt][nt][0], WB0[kt][nt][1]);
                    mma16816(C[nt][0], C[nt][1], C[nt][2], C[nt][3],
                             AL[kt][0], AL[kt][1], AL[kt][2], AL[kt][3],
                             WB0[kt][nt][0], WB0[kt][nt][1]);
                }
            }

            // ---- quantize -> layer-2 A fragments ----
            unsigned A[2][4];
            #pragma unroll
            for (int kn = 0; kn < 2; kn++) {
                int n0 = 2 * kn, n1 = 2 * kn + 1;
                A[kn][0] = packh2(qrelu_p(C[n0][0]), qrelu_p(C[n0][1]));
                A[kn][1] = packh2(qrelu_p(C[n0][2]), qrelu_p(C[n0][3]));
                A[kn][2] = packh2(qrelu_p(C[n1][0]), qrelu_p(C[n1][1]));
                A[kn][3] = packh2(qrelu_p(C[n1][2]), qrelu_p(C[n1][3]));
            }

            // ---- layer 2 ----
            #pragma unroll
            for (int nt = 0; nt < 4; nt++) {
                C[nt][0] = be1[nt]; C[nt][1] = bo1[nt];
                C[nt][2] = be1[nt]; C[nt][3] = bo1[nt];
                #pragma unroll
                for (int kt = 0; kt < 2; kt++)
                    mma16816(C[nt][0], C[nt][1], C[nt][2], C[nt][3],
                             A[kt][0], A[kt][1], A[kt][2], A[kt][3],
                             WB1[kt][nt][0], WB1[kt][nt][1]);
            }

            #pragma unroll
            for (int kn = 0; kn < 2; kn++) {
                int n0 = 2 * kn, n1 = 2 * kn + 1;
                A[kn][0] = packh2(qrelu_p(C[n0][0]), qrelu_p(C[n0][1]));
                A[kn][1] = packh2(qrelu_p(C[n0][2]), qrelu_p(C[n0][3]));
                A[kn][2] = packh2(qrelu_p(C[n1][0]), qrelu_p(C[n1][1]));
                A[kn][3] = packh2(qrelu_p(C[n1][2]), qrelu_p(C[n1][3]));
            }

            // ---- layer 3: outputs live in cols 0/1 of t==0 lanes ----
            float D[4];
            D[0] = beo; D[1] = boo; D[2] = beo; D[3] = boo;
            #pragma unroll
            for (int kt = 0; kt < 2; kt++)
                mma16816(D[0], D[1], D[2], D[3],
                         A[kt][0], A[kt][1], A[kt][2], A[kt][3],
                         WB2[kt][0], WB2[kt][1]);

            // ---- epilogue: raw = qfin(y3)/256 ----
            if (t == 0) {
                #pragma unroll
                for (int half = 0; half < 2; half++) {
                    long long row = rb + 16 * mt + g + (half ? 8 : 0);
                    float mu = qfin(D[half ? 2 : 0]) * 0.00390625f;
                    float ls = qfin(D[half ? 3 : 1]) * 0.00390625f;
                    float sc = __expf(fminf(fmaxf(ls - 4.0f, -4.6f), 5.0f));
                    if (!GUARD || row < B) {
                        out[row]         = mu;
                        out[B + row]     = sc;
                        out[2 * B + row] = ls;
                    }
                }
            }
        }
    }
    #undef ISSUE_TILE
}

extern "C" void kernel_launch(void* const* d_in, const int* in_sizes, int n_in,
                              void* d_out, int out_size)
{
    const float* x     = (const float*)d_in[0];
    const float* w0    = (const float*)d_in[1];
    const float* b0    = (const float*)d_in[2];
    const float* w1    = (const float*)d_in[3];
    const float* b1    = (const float*)d_in[4];
    const float* w_out = (const float*)d_in[5];
    const float* b_out = (const float*)d_in[6];

    const long long B = in_sizes[0] / 32;
    const long long rows_per_block = 128LL * ITERS;
    const int grid = (int)((B + rows_per_block - 1) / rows_per_block);

    if (B % rows_per_block == 0) {
        cudaFuncSetAttribute(armint_kernel<false>,
                             cudaFuncAttributeMaxDynamicSharedMemorySize, SMEM_TOTAL);
        armint_kernel<false><<<grid, BLOCK, SMEM_TOTAL>>>(
            x, w0, b0, w1, b1, w_out, b_out, (float*)d_out, B);
    } else {
        cudaFuncSetAttribute(armint_kernel<true>,
                             cudaFuncAttributeMaxDynamicSharedMemorySize, SMEM_TOTAL);
        armint_kernel<true><<<grid, BLOCK, SMEM_TOTAL>>>(
            x, w0, b0, w1, b1, w_out, b_out, (float*)d_out, B);
    }
}